// round 14
// baseline (speedup 1.0000x reference)
#include <cuda_runtime.h>
#include <cuda_fp16.h>
#include <mma.h>
#include <math.h>
#include <cstdint>

using namespace nvcuda;

#define NB   32
#define LK   4096
#define DM   512
#define NH   8
#define DH   64
#define DFF  2048
#define LQ   22
#define SKK  45
#define NTOP 20
#define ROWS 176
#define RPAD 192
#define MROWS (NB * LQ)      // 704
#define MPAD  768

// ---------------- scratch (zero-initialized device globals) ----------------
__device__ float g_qw[RPAD * DM];
__device__ __half g_qwh[256 * DM];                 // rows >=176 stay 0
__device__ __half g_ench[(size_t)NB * LK * DM];
__device__ float g_sc[NB * ROWS * 48];
__device__ unsigned char g_istop[NB * ROWS];
__device__ __half g_Sh[(size_t)NB * RPAD * LK];
__device__ float g_psum[NB * RPAD * 32];
__device__ float g_encsum[NB * DM];
__device__ __half g_uh[4 * (size_t)NB * RPAD * DM];
__device__ float g_ctx[MPAD * DM];
__device__ float g_ao[MROWS * DM];
__device__ float g_x[MPAD * DM];
__device__ __half g_xh[MPAD * DM];
__device__ __half g_w1h[DFF * DM];
__device__ __half g_w2h[DM * DFF];
__device__ __half g_ffh[(size_t)MPAD * DFF];
__device__ float g_zp[4 * (size_t)MROWS * DM];

// ---------------- async-copy helpers ----------------
__device__ __forceinline__ void cp16(void* smem, const void* gmem) {
    uint32_t s = (uint32_t)__cvta_generic_to_shared(smem);
    asm volatile("cp.async.cg.shared.global [%0], [%1], 16;" :: "r"(s), "l"(gmem));
}
__device__ __forceinline__ void cp_commit() { asm volatile("cp.async.commit_group;"); }
template<int N> __device__ __forceinline__ void cp_wait() {
    asm volatile("cp.async.wait_group %0;" :: "n"(N));
}

__device__ __forceinline__ float blockReduce(float v, float* red) {
    __syncthreads();
    #pragma unroll
    for (int o = 16; o; o >>= 1) v += __shfl_down_sync(0xffffffffu, v, o);
    int w = threadIdx.x >> 5;
    if ((threadIdx.x & 31) == 0) red[w] = v;
    __syncthreads();
    if (threadIdx.x < 32) {
        float x = (threadIdx.x < (blockDim.x >> 5)) ? red[threadIdx.x] : 0.f;
        #pragma unroll
        for (int o = 16; o; o >>= 1) x += __shfl_down_sync(0xffffffffu, x, o);
        if (threadIdx.x == 0) red[0] = x;
    }
    __syncthreads();
    return red[0];
}

// ================= L1: enc_cvt (0..2047) | qw (2048..2223) | wcvt (2224+) ====
__global__ void __launch_bounds__(256) l1_kernel(const float* __restrict__ enc,
                                                 const float* __restrict__ Wq,
                                                 const float* __restrict__ bq,
                                                 const float* __restrict__ Wk,
                                                 const float* __restrict__ w1,
                                                 const float* __restrict__ w2) {
    int blk = blockIdx.x, t = threadIdx.x;
    if (blk < 2048) {                              // ---- enc_cvt ----
        __shared__ float ssum[DM];
        int b = blk >> 6, l0 = (blk & 63) * 64;
        int c8 = (t & 63) * 8, rg = t >> 6;
        for (int i = t; i < DM; i += 256) ssum[i] = 0.f;
        __syncthreads();
        float acc[8];
        #pragma unroll
        for (int k = 0; k < 8; k++) acc[k] = 0.f;
        const float* src = enc + ((size_t)b * LK + l0) * DM + c8;
        __half* dst = g_ench + ((size_t)b * LK + l0) * DM + c8;
        #pragma unroll
        for (int i = 0; i < 16; i++) {
            int r = rg + 4 * i;
            float4 v0 = __ldg((const float4*)(src + (size_t)r * DM));
            float4 v1 = __ldg((const float4*)(src + (size_t)r * DM + 4));
            acc[0] += v0.x; acc[1] += v0.y; acc[2] += v0.z; acc[3] += v0.w;
            acc[4] += v1.x; acc[5] += v1.y; acc[6] += v1.z; acc[7] += v1.w;
            __half h8[8];
            h8[0] = __float2half_rn(v0.x); h8[1] = __float2half_rn(v0.y);
            h8[2] = __float2half_rn(v0.z); h8[3] = __float2half_rn(v0.w);
            h8[4] = __float2half_rn(v1.x); h8[5] = __float2half_rn(v1.y);
            h8[6] = __float2half_rn(v1.z); h8[7] = __float2half_rn(v1.w);
            *(uint4*)(dst + (size_t)r * DM) = *(uint4*)h8;
        }
        #pragma unroll
        for (int k = 0; k < 8; k++) atomicAdd(&ssum[c8 + k], acc[k]);
        __syncthreads();
        for (int c = t; c < DM; c += 256) atomicAdd(&g_encsum[b * DM + c], ssum[c]);
        return;
    }
    if (blk < 2048 + 176) {                        // ---- qw rows ----
        int row = blk - 2048, h = row / LQ, q = row % LQ;
        __shared__ float spe[DM];
        __shared__ float sq[64];
        const float c = logf(10000.0f) / 512.0f;
        for (int j = t; j < DM; j += 256) {
            int i = j >> 1;
            float arg = (float)q * expf(-(float)(2 * i) * c);
            spe[j] = (j & 1) ? cosf(arg) : sinf(arg);
        }
        __syncthreads();
        if (t < 64) {
            float a = bq[h * 64 + t];
            for (int k = 0; k < DM; k++) a += spe[k] * Wq[k * DM + h * 64 + t];
            sq[t] = a;
        }
        __syncthreads();
        for (int c2 = t; c2 < DM; c2 += 256) {
            const float* wr = Wk + (size_t)c2 * DM + h * 64;
            float a = 0.f;
            #pragma unroll
            for (int d = 0; d < 64; d++) a += sq[d] * wr[d];
            g_qw[row * DM + c2] = a;
            g_qwh[row * DM + c2] = __float2half_rn(a);
        }
        return;
    }
    {                                              // ---- weight cvt ----
        int i = ((blk - 2048 - 176) * 256 + t) * 4;
        if (i < DFF * DM) {
            float4 v = *(const float4*)(w1 + i);
            __half h4[4] = {__float2half_rn(v.x), __float2half_rn(v.y),
                            __float2half_rn(v.z), __float2half_rn(v.w)};
            *(uint2*)(g_w1h + i) = *(uint2*)h4;
            float4 u = *(const float4*)(w2 + i);
            __half g4[4] = {__float2half_rn(u.x), __float2half_rn(u.y),
                            __float2half_rn(u.z), __float2half_rn(u.w)};
            *(uint2*)(g_w2h + i) = *(uint2*)g4;
        }
    }
}

// ---- zero encsum (tiny, merged into L1? encsum is accumulated by enc_cvt; must
// be zeroed BEFORE L1. Poisoned buffer -> explicit zero kernel first.) --------
__global__ void zero_kernel() {
    int i = blockIdx.x * 256 + threadIdx.x;
    if (i < NB * DM) g_encsum[i] = 0.f;
}

// ================= L2: s_gemm (0..2047) | samp_score (2048+) =================
#define SHSTG 16128  // halfs per stage: A 96*72 + B 128*72
__global__ void __launch_bounds__(256, 3) l2_kernel(const float* __restrict__ enc) {
    extern __shared__ __align__(16) char smraw[];
    int blk = blockIdx.x, t = threadIdx.x;
    if (blk >= 2048) {                             // ---- samp_score ----
        int idx = blk - 2048;
        int b = idx / SKK, s = idx % SKK;
        int warp = t >> 5, lane = t & 31;
        float* se = (float*)smraw;
        int l = (s * LK) / SKK;
        for (int j = t; j < DM; j += 256) se[j] = enc[((size_t)b * LK + l) * DM + j];
        __syncthreads();
        const float4* se4 = (const float4*)se;
        for (int row = warp; row < ROWS; row += 8) {
            const float4* qw4 = (const float4*)(g_qw + row * DM);
            float a = 0.f;
            #pragma unroll
            for (int k = 0; k < 4; k++) {
                int i2 = lane + k * 32;
                float4 q = qw4[i2], e = se4[i2];
                a += q.x * e.x + q.y * e.y + q.z * e.z + q.w * e.w;
            }
            #pragma unroll
            for (int o = 16; o; o >>= 1) a += __shfl_down_sync(0xffffffffu, a, o);
            if (lane == 0) g_sc[(b * ROWS + row) * 48 + s] = a;
        }
        return;
    }
    // ---- s_gemm ----
    int warp = t >> 5;
    int nt = (blk & 63) >> 1, mt = blk & 1, b = blk >> 6;
    int m0 = mt * 96, n0 = nt * 128;
    int wm = warp >> 2, wn = warp & 3;
    const __half* Ag = g_qwh + (size_t)m0 * DM;
    const __half* Bg = g_ench + ((size_t)b * LK + n0) * DM;

    auto loadStage = [&](int st, int k0) {
        __half* As = (__half*)smraw + st * SHSTG;
        __half* Bs = As + 6912;
        #pragma unroll
        for (int i4 = t; i4 < 768; i4 += 256) {
            int r = i4 >> 3, c8 = (i4 & 7) * 8;
            cp16(As + r * 72 + c8, Ag + (size_t)r * DM + k0 + c8);
        }
        #pragma unroll
        for (int i4 = t; i4 < 1024; i4 += 256) {
            int l = i4 >> 3, c8 = (i4 & 7) * 8;
            cp16(Bs + l * 72 + c8, Bg + (size_t)l * DM + k0 + c8);
        }
        cp_commit();
    };

    wmma::fragment<wmma::accumulator, 16, 16, 16, float> acc[3][2];
    #pragma unroll
    for (int i = 0; i < 3; i++)
        #pragma unroll
        for (int j = 0; j < 2; j++) wmma::fill_fragment(acc[i][j], 0.0f);

    loadStage(0, 0);
    for (int ks = 0; ks < 8; ks++) {
        cp_wait<0>();
        __syncthreads();
        if (ks + 1 < 8) loadStage((ks + 1) & 1, (ks + 1) * 64);
        __half* As = (__half*)smraw + (ks & 1) * SHSTG;
        __half* Bs = As + 6912;
        #pragma unroll
        for (int kk = 0; kk < 4; kk++) {
            wmma::fragment<wmma::matrix_a, 16, 16, 16, __half, wmma::row_major> af[3];
            wmma::fragment<wmma::matrix_b, 16, 16, 16, __half, wmma::col_major> bf[2];
            #pragma unroll
            for (int i = 0; i < 3; i++)
                wmma::load_matrix_sync(af[i], As + (wm * 48 + i * 16) * 72 + kk * 16, 72);
            #pragma unroll
            for (int j = 0; j < 2; j++)
                wmma::load_matrix_sync(bf[j], Bs + (wn * 32 + j * 16) * 72 + kk * 16, 72);
            #pragma unroll
            for (int i = 0; i < 3; i++)
                #pragma unroll
                for (int j = 0; j < 2; j++) wmma::mma_sync(acc[i][j], af[i], bf[j], acc[i][j]);
        }
    }
    __syncthreads();
    float* Ss = (float*)smraw;  // [96][132]
    #pragma unroll
    for (int i = 0; i < 3; i++)
        #pragma unroll
        for (int j = 0; j < 2; j++)
            wmma::store_matrix_sync(Ss + (wm * 48 + i * 16) * 132 + wn * 32 + j * 16,
                                    acc[i][j], 132, wmma::mem_row_major);
    __syncthreads();
    size_t base = ((size_t)b * RPAD + m0) * LK + n0;
    __shared__ float srow[96];
    if (t < 96) srow[t] = 0.f;
    __syncthreads();
    int lane = t & 31;
    for (int i4 = t; i4 < 3072; i4 += 256) {
        int r = i4 >> 5, c4 = (i4 & 31) * 4;
        float4 v = *(float4*)(Ss + r * 132 + c4);
        float e0 = __expf(v.x * 0.125f), e1 = __expf(v.y * 0.125f);
        float e2 = __expf(v.z * 0.125f), e3 = __expf(v.w * 0.125f);
        __half h4[4];
        h4[0] = __float2half_rn(e0); h4[1] = __float2half_rn(e1);
        h4[2] = __float2half_rn(e2); h4[3] = __float2half_rn(e3);
        *(uint2*)(g_Sh + base + (size_t)r * LK + c4) = *(uint2*)h4;
        float s4 = e0 + e1 + e2 + e3;
        #pragma unroll
        for (int o = 16; o; o >>= 1) s4 += __shfl_down_sync(0xffffffffu, s4, o);
        if (lane == 0) srow[r] = s4;
    }
    __syncthreads();
    if (t < 96) g_psum[((size_t)b * RPAD + m0 + t) * 32 + nt] = srow[t];
}

// ================= L3: u_gemm (0..1023) | samp_select (1024+) ================
#define UHSTG 15616  // halfs per stage: A 96*72 + B 64*136
__global__ void __launch_bounds__(256, 3) l3_kernel(int dummy) {
    extern __shared__ __align__(16) char smraw[];
    int blk = blockIdx.x, t = threadIdx.x;
    if (blk >= 1024) {                             // ---- samp_select ----
        int b = blk - 1024;
        float* sM = (float*)smraw;                 // [176]
        if (t < ROWS) {
            const float* sc = g_sc + (b * ROWS + t) * 48;
            float mx = -1e30f, su = 0.f;
            for (int s = 0; s < SKK; s++) { float v = sc[s]; mx = fmaxf(mx, v); su += v; }
            sM[t] = mx - su * (1.0f / SKK);
        }
        __syncthreads();
        if (t < ROWS) {
            int h = t / LQ, q = t % LQ, base = h * LQ, rank = 0;
            float mv = sM[t];
            for (int i = 0; i < LQ; i++) {
                float o = sM[base + i];
                rank += (o > mv) || (o == mv && i < q);
            }
            g_istop[b * ROWS + t] = (rank < NTOP) ? 1 : 0;
        }
        return;
    }
    // ---- u_gemm ----
    int warp = t >> 5;
    int gx = blk & 31, b = blk >> 5;
    int nt = gx & 3, mt = (gx >> 2) & 1, kc = gx >> 3;
    int m0 = mt * 96, n0 = nt * 128;
    int wm = warp >> 2, wn = warp & 3;
    const __half* Ag = g_Sh + ((size_t)b * RPAD + m0) * LK + kc * 1024;
    const __half* Bg = g_ench + ((size_t)b * LK + kc * 1024) * DM + n0;

    auto loadStage = [&](int st, int k0) {
        __half* As = (__half*)smraw + st * UHSTG;
        __half* Bs = As + 6912;
        #pragma unroll
        for (int i4 = t; i4 < 768; i4 += 256) {
            int r = i4 >> 3, c8 = (i4 & 7) * 8;
            cp16(As + r * 72 + c8, Ag + (size_t)r * LK + k0 + c8);
        }
        #pragma unroll
        for (int i4 = t; i4 < 1024; i4 += 256) {
            int l = i4 >> 4, c8 = (i4 & 15) * 8;
            cp16(Bs + l * 136 + c8, Bg + (size_t)(k0 + l) * DM + c8);
        }
        cp_commit();
    };

    wmma::fragment<wmma::accumulator, 16, 16, 16, float> acc[3][2];
    #pragma unroll
    for (int i = 0; i < 3; i++)
        #pragma unroll
        for (int j = 0; j < 2; j++) wmma::fill_fragment(acc[i][j], 0.0f);

    loadStage(0, 0);
    for (int ks = 0; ks < 16; ks++) {
        cp_wait<0>();
        __syncthreads();
        if (ks + 1 < 16) loadStage((ks + 1) & 1, (ks + 1) * 64);
        __half* As = (__half*)smraw + (ks & 1) * UHSTG;
        __half* Bs = As + 6912;
        #pragma unroll
        for (int kk = 0; kk < 4; kk++) {
            wmma::fragment<wmma::matrix_a, 16, 16, 16, __half, wmma::row_major> af[3];
            wmma::fragment<wmma::matrix_b, 16, 16, 16, __half, wmma::row_major> bf[2];
            #pragma unroll
            for (int i = 0; i < 3; i++)
                wmma::load_matrix_sync(af[i], As + (wm * 48 + i * 16) * 72 + kk * 16, 72);
            #pragma unroll
            for (int j = 0; j < 2; j++)
                wmma::load_matrix_sync(bf[j], Bs + (kk * 16) * 136 + wn * 32 + j * 16, 136);
            #pragma unroll
            for (int i = 0; i < 3; i++)
                #pragma unroll
                for (int j = 0; j < 2; j++) wmma::mma_sync(acc[i][j], af[i], bf[j], acc[i][j]);
        }
    }
    __syncthreads();
    float* Ss = (float*)smraw;  // [96][132]
    #pragma unroll
    for (int i = 0; i < 3; i++)
        #pragma unroll
        for (int j = 0; j < 2; j++)
            wmma::store_matrix_sync(Ss + (wm * 48 + i * 16) * 132 + wn * 32 + j * 16,
                                    acc[i][j], 132, wmma::mem_row_major);
    __syncthreads();
    __half* up = g_uh + (size_t)kc * NB * RPAD * DM + ((size_t)(b * RPAD + m0)) * DM + n0;
    for (int i4 = t; i4 < 3072; i4 += 256) {
        int r = i4 >> 5, c4 = (i4 & 31) * 4;
        float4 v = *(float4*)(Ss + r * 132 + c4);
        __half h4[4];
        h4[0] = __float2half_rn(v.x); h4[1] = __float2half_rn(v.y);
        h4[2] = __float2half_rn(v.z); h4[3] = __float2half_rn(v.w);
        *(uint2*)(up + (size_t)r * DM + c4) = *(uint2*)h4;
    }
}

// ---------------- ctx ----------------
__global__ void ctx_kernel(const float* __restrict__ Wv, const float* __restrict__ bv) {
    __shared__ float su[LQ * DM];
    __shared__ float svm[64];
    __shared__ float srinv[LQ];
    int bh = blockIdx.x, b = bh >> 3, h = bh & 7, t = threadIdx.x;
    const size_t ub = ((size_t)b * RPAD + h * LQ) * DM;
    const size_t part = (size_t)NB * RPAD * DM;
    if (t < LQ) {
        const float* ps = g_psum + ((size_t)b * RPAD + h * LQ + t) * 32;
        float s = 0.f;
        #pragma unroll
        for (int i = 0; i < 32; i++) s += ps[i];
        srinv[t] = 1.0f / s;
    }
    __syncthreads();
    for (int i = t; i < LQ * DM; i += 256) {
        int q = i >> 9;
        float s = __half2float(g_uh[ub + i]) + __half2float(g_uh[part + ub + i])
                + __half2float(g_uh[2 * part + ub + i]) + __half2float(g_uh[3 * part + ub + i]);
        su[i] = s * srinv[q];
    }
    if (t < 64) {
        float a = bv[h * 64 + t];
        const float inv = 1.0f / 4096.f;
        for (int c = 0; c < DM; c++) a += g_encsum[b * DM + c] * inv * Wv[c * DM + h * 64 + t];
        svm[t] = a;
    }
    __syncthreads();
    for (int i = t; i < LQ * 64; i += 256) {
        int q = i >> 6, d = i & 63;
        float v;
        if (g_istop[b * ROWS + h * LQ + q]) {
            float a = bv[h * 64 + d];
            for (int c = 0; c < DM; c++) a += su[q * DM + c] * Wv[c * DM + h * 64 + d];
            v = a;
        } else v = svm[d];
        g_ctx[((size_t)b * LQ + q) * DM + h * 64 + d] = v;
    }
}

// ---------------- o GEMM (tf32) ----------------
#define OSTG 7680
__global__ void __launch_bounds__(256) o_gemm(const float* __restrict__ Wo,
                                              const float* __restrict__ bo) {
    extern __shared__ __align__(16) char smraw[];
    float* smd = (float*)smraw;
    int t = threadIdx.x, warp = t >> 5;
    int m0 = blockIdx.y * 96, n0 = blockIdx.x * 128;
    int wm = warp >> 2, wn = warp & 3;
    const float* Ag = g_ctx + (size_t)m0 * DM;
    const float* Bg = Wo + n0;

    auto loadStage = [&](int st, int k0) {
        float* As = smd + st * OSTG;
        float* Bs = As + 3456;
        #pragma unroll
        for (int i4 = t; i4 < 768; i4 += 256) {
            int r = i4 >> 3, c4 = (i4 & 7) * 4;
            cp16(As + r * 36 + c4, Ag + (size_t)r * DM + k0 + c4);
        }
        #pragma unroll
        for (int i4 = t; i4 < 1024; i4 += 256) {
            int l = i4 >> 5, c4 = (i4 & 31) * 4;
            cp16(Bs + l * 132 + c4, Bg + (size_t)(k0 + l) * DM + c4);
        }
        cp_commit();
    };

    wmma::fragment<wmma::accumulator, 16, 16, 8, float> acc[3][2];
    #pragma unroll
    for (int i = 0; i < 3; i++)
        #pragma unroll
        for (int j = 0; j < 2; j++) wmma::fill_fragment(acc[i][j], 0.0f);

    loadStage(0, 0);
    loadStage(1, 32);
    for (int ks = 0; ks < 16; ks++) {
        if (ks < 15) cp_wait<1>(); else cp_wait<0>();
        __syncthreads();
        if (ks + 2 < 16) loadStage((ks + 2) % 3, (ks + 2) * 32);
        float* As = smd + (ks % 3) * OSTG;
        float* Bs = As + 3456;
        #pragma unroll
        for (int kk = 0; kk < 4; kk++) {
            wmma::fragment<wmma::matrix_a, 16, 16, 8, wmma::precision::tf32, wmma::row_major> af[3];
            wmma::fragment<wmma::matrix_b, 16, 16, 8, wmma::precision::tf32, wmma::row_major> bf[2];
            #pragma unroll
            for (int i = 0; i < 3; i++) {
                wmma::load_matrix_sync(af[i], As + (wm * 48 + i * 16) * 36 + kk * 8, 36);
                #pragma unroll
                for (int e = 0; e < af[i].num_elements; e++) af[i].x[e] = wmma::__float_to_tf32(af[i].x[e]);
            }
            #pragma unroll
            for (int j = 0; j < 2; j++) {
                wmma::load_matrix_sync(bf[j], Bs + (kk * 8) * 132 + wn * 32 + j * 16, 132);
                #pragma unroll
                for (int e = 0; e < bf[j].num_elements; e++) bf[j].x[e] = wmma::__float_to_tf32(bf[j].x[e]);
            }
            #pragma unroll
            for (int i = 0; i < 3; i++)
                #pragma unroll
                for (int j = 0; j < 2; j++) wmma::mma_sync(acc[i][j], af[i], bf[j], acc[i][j]);
        }
    }
    __syncthreads();
    float* Ss = smd;
    #pragma unroll
    for (int i = 0; i < 3; i++)
        #pragma unroll
        for (int j = 0; j < 2; j++)
            wmma::store_matrix_sync(Ss + (wm * 48 + i * 16) * 132 + wn * 32 + j * 16,
                                    acc[i][j], 132, wmma::mem_row_major);
    __syncthreads();
    for (int i4 = t; i4 < 3072; i4 += 256) {
        int r = i4 >> 5, c4 = (i4 & 31) * 4;
        int row = m0 + r, n = n0 + c4;
        if (row >= MROWS) continue;
        float4 v = *(float4*)(Ss + r * 132 + c4);
        v.x = 2.0f * (v.x + bo[n + 0]); v.y = 2.0f * (v.y + bo[n + 1]);
        v.z = 2.0f * (v.z + bo[n + 2]); v.w = 2.0f * (v.w + bo[n + 3]);
        *(float4*)(g_ao + (size_t)row * DM + n) = v;
    }
}

// ---------------- ln1 ----------------
__global__ void ln1_kernel(const float* __restrict__ g1, const float* __restrict__ be1) {
    int r = blockIdx.x, t = threadIdx.x;
    __shared__ float red[32];
    float z0 = g_ao[(size_t)r * DM + t];
    float z1 = g_ao[(size_t)r * DM + t + 256];
    float s1 = blockReduce(z0 + z1, red);
    float s2 = blockReduce(z0 * z0 + z1 * z1, red);
    float mu = s1 * (1.0f / 512.f);
    float va = fmaxf(s2 * (1.0f / 512.f) - mu * mu, 0.f);
    float rs = rsqrtf(va + 1e-5f);
    float x0 = (z0 - mu) * rs * g1[t] + be1[t];
    float x1 = (z1 - mu) * rs * g1[t + 256] + be1[t + 256];
    g_x[(size_t)r * DM + t] = x0;
    g_x[(size_t)r * DM + t + 256] = x1;
    g_xh[(size_t)r * DM + t] = __float2half_rn(x0);
    g_xh[(size_t)r * DM + t + 256] = __float2half_rn(x1);
}

// ---------------- ffn1 ----------------
__global__ void __launch_bounds__(256, 3) ffn1_gemm(const float* __restrict__ b1) {
    extern __shared__ __align__(16) char smraw[];
    int t = threadIdx.x, warp = t >> 5;
    int m0 = blockIdx.y * 96, n0 = blockIdx.x * 128;
    int wm = warp >> 2, wn = warp & 3;
    const __half* Ag = g_xh + (size_t)m0 * DM;
    const __half* Bg = g_w1h + (size_t)n0 * DM;

    auto loadStage = [&](int st, int k0) {
        __half* As = (__half*)smraw + st * SHSTG;
        __half* Bs = As + 6912;
        #pragma unroll
        for (int i4 = t; i4 < 768; i4 += 256) {
            int r = i4 >> 3, c8 = (i4 & 7) * 8;
            cp16(As + r * 72 + c8, Ag + (size_t)r * DM + k0 + c8);
        }
        #pragma unroll
        for (int i4 = t; i4 < 1024; i4 += 256) {
            int n = i4 >> 3, c8 = (i4 & 7) * 8;
            cp16(Bs + n * 72 + c8, Bg + (size_t)n * DM + k0 + c8);
        }
        cp_commit();
    };

    wmma::fragment<wmma::accumulator, 16, 16, 16, float> acc[3][2];
    #pragma unroll
    for (int i = 0; i < 3; i++)
        #pragma unroll
        for (int j = 0; j < 2; j++) wmma::fill_fragment(acc[i][j], 0.0f);

    loadStage(0, 0);
    for (int ks = 0; ks < 8; ks++) {
        cp_wait<0>();
        __syncthreads();
        if (ks + 1 < 8) loadStage((ks + 1) & 1, (ks + 1) * 64);
        __half* As = (__half*)smraw + (ks & 1) * SHSTG;
        __half* Bs = As + 6912;
        #pragma unroll
        for (int kk = 0; kk < 4; kk++) {
            wmma::fragment<wmma::matrix_a, 16, 16, 16, __half, wmma::row_major> af[3];
            wmma::fragment<wmma::matrix_b, 16, 16, 16, __half, wmma::col_major> bf[2];
            #pragma unroll
            for (int i = 0; i < 3; i++)
                wmma::load_matrix_sync(af[i], As + (wm * 48 + i * 16) * 72 + kk * 16, 72);
            #pragma unroll
            for (int j = 0; j < 2; j++)
                wmma::load_matrix_sync(bf[j], Bs + (wn * 32 + j * 16) * 72 + kk * 16, 72);
            #pragma unroll
            for (int i = 0; i < 3; i++)
                #pragma unroll
                for (int j = 0; j < 2; j++) wmma::mma_sync(acc[i][j], af[i], bf[j], acc[i][j]);
        }
    }
    __syncthreads();
    float* Ss = (float*)smraw;
    #pragma unroll
    for (int i = 0; i < 3; i++)
        #pragma unroll
        for (int j = 0; j < 2; j++)
            wmma::store_matrix_sync(Ss + (wm * 48 + i * 16) * 132 + wn * 32 + j * 16,
                                    acc[i][j], 132, wmma::mem_row_major);
    __syncthreads();
    for (int i4 = t; i4 < 3072; i4 += 256) {
        int r = i4 >> 5, c4 = (i4 & 31) * 4;
        int row = m0 + r, n = n0 + c4;
        if (row >= MROWS) continue;
        float4 v = *(float4*)(Ss + r * 132 + c4);
        __half h4[4];
        h4[0] = __float2half_rn(fmaxf(v.x + b1[n + 0], 0.f));
        h4[1] = __float2half_rn(fmaxf(v.y + b1[n + 1], 0.f));
        h4[2] = __float2half_rn(fmaxf(v.z + b1[n + 2], 0.f));
        h4[3] = __float2half_rn(fmaxf(v.w + b1[n + 3], 0.f));
        *(uint2*)(g_ffh + (size_t)row * DFF + n) = *(uint2*)h4;
    }
}

// ---------------- ffn2 ----------------
__global__ void __launch_bounds__(256, 3) ffn2_gemm(int dummy) {
    extern __shared__ __align__(16) char smraw[];
    int t = threadIdx.x, warp = t >> 5;
    int m0 = blockIdx.y * 96, n0 = blockIdx.x * 128, kc = blockIdx.z;
    int wm = warp >> 2, wn = warp & 3;
    const __half* Ag = g_ffh + (size_t)m0 * DFF + kc * 512;
    const __half* Bg = g_w2h + (size_t)n0 * DFF + kc * 512;

    auto loadStage = [&](int st, int k0) {
        __half* As = (__half*)smraw + st * SHSTG;
        __half* Bs = As + 6912;
        #pragma unroll
        for (int i4 = t; i4 < 768; i4 += 256) {
            int r = i4 >> 3, c8 = (i4 & 7) * 8;
            cp16(As + r * 72 + c8, Ag + (size_t)r * DFF + k0 + c8);
        }
        #pragma unroll
        for (int i4 = t; i4 < 1024; i4 += 256) {
            int n = i4 >> 3, c8 = (i4 & 7) * 8;
            cp16(Bs + n * 72 + c8, Bg + (size_t)n * DFF + k0 + c8);
        }
        cp_commit();
    };

    wmma::fragment<wmma::accumulator, 16, 16, 16, float> acc[3][2];
    #pragma unroll
    for (int i = 0; i < 3; i++)
        #pragma unroll
        for (int j = 0; j < 2; j++) wmma::fill_fragment(acc[i][j], 0.0f);

    loadStage(0, 0);
    for (int ks = 0; ks < 8; ks++) {
        cp_wait<0>();
        __syncthreads();
        if (ks + 1 < 8) loadStage((ks + 1) & 1, (ks + 1) * 64);
        __half* As = (__half*)smraw + (ks & 1) * SHSTG;
        __half* Bs = As + 6912;
        #pragma unroll
        for (int kk = 0; kk < 4; kk++) {
            wmma::fragment<wmma::matrix_a, 16, 16, 16, __half, wmma::row_major> af[3];
            wmma::fragment<wmma::matrix_b, 16, 16, 16, __half, wmma::col_major> bf[2];
            #pragma unroll
            for (int i = 0; i < 3; i++)
                wmma::load_matrix_sync(af[i], As + (wm * 48 + i * 16) * 72 + kk * 16, 72);
            #pragma unroll
            for (int j = 0; j < 2; j++)
                wmma::load_matrix_sync(bf[j], Bs + (wn * 32 + j * 16) * 72 + kk * 16, 72);
            #pragma unroll
            for (int i = 0; i < 3; i++)
                #pragma unroll
                for (int j = 0; j < 2; j++) wmma::mma_sync(acc[i][j], af[i], bf[j], acc[i][j]);
        }
    }
    __syncthreads();
    float* Ss = (float*)smraw;
    #pragma unroll
    for (int i = 0; i < 3; i++)
        #pragma unroll
        for (int j = 0; j < 2; j++)
            wmma::store_matrix_sync(Ss + (wm * 48 + i * 16) * 132 + wn * 32 + j * 16,
                                    acc[i][j], 132, wmma::mem_row_major);
    __syncthreads();
    float* Cp = g_zp + (size_t)kc * MROWS * DM;
    for (int i4 = t; i4 < 3072; i4 += 256) {
        int r = i4 >> 5, c4 = (i4 & 31) * 4;
        int row = m0 + r, n = n0 + c4;
        if (row >= MROWS) continue;
        *(float4*)(Cp + (size_t)row * DM + n) = *(float4*)(Ss + r * 132 + c4);
    }
}

// ---------------- f3b ----------------
__global__ void f3b_kernel(const float* __restrict__ b2,
                           const float* __restrict__ g2, const float* __restrict__ be2,
                           const float* __restrict__ Wout, const float* __restrict__ bout,
                           float* __restrict__ out) {
    int r = blockIdx.x, t = threadIdx.x;
    __shared__ float red[32];
    const size_t part = (size_t)MROWS * DM;
    size_t o0 = (size_t)r * DM + t, o1 = o0 + 256;
    float z0 = g_x[o0] + b2[t] + g_zp[o0] + g_zp[part + o0] + g_zp[2 * part + o0] + g_zp[3 * part + o0];
    float z1 = g_x[o1] + b2[t + 256] + g_zp[o1] + g_zp[part + o1] + g_zp[2 * part + o1] + g_zp[3 * part + o1];
    float s1 = blockReduce(z0 + z1, red);
    float s2 = blockReduce(z0 * z0 + z1 * z1, red);
    float mu = s1 * (1.0f / 512.f);
    float va = fmaxf(s2 * (1.0f / 512.f) - mu * mu, 0.f);
    float rs = rsqrtf(va + 1e-5f);
    float y0 = (z0 - mu) * rs * g2[t] + be2[t];
    float y1 = (z1 - mu) * rs * g2[t + 256] + be2[t + 256];
    out[NB * LQ + (size_t)r * DM + t] = y0;
    out[NB * LQ + (size_t)r * DM + t + 256] = y1;
    float f = blockReduce(y0 * Wout[t] + y1 * Wout[t + 256], red);
    if (t == 0) out[r] = f + bout[0];
}

// ---------------- launch ----------------
extern "C" void kernel_launch(void* const* d_in, const int* in_sizes, int n_in,
                              void* d_out, int out_size) {
    const float* enc  = (const float*)d_in[0];
    const float* Wq   = (const float*)d_in[1];
    const float* bq   = (const float*)d_in[2];
    const float* Wk   = (const float*)d_in[3];
    const float* Wv   = (const float*)d_in[5];
    const float* bv   = (const float*)d_in[6];
    const float* Wo   = (const float*)d_in[7];
    const float* bo   = (const float*)d_in[8];
    const float* w1   = (const float*)d_in[9];
    const float* b1   = (const float*)d_in[10];
    const float* w2   = (const float*)d_in[11];
    const float* b2   = (const float*)d_in[12];
    const float* g1   = (const float*)d_in[13];
    const float* be1  = (const float*)d_in[14];
    const float* g2   = (const float*)d_in[15];
    const float* be2  = (const float*)d_in[16];
    const float* Wout = (const float*)d_in[17];
    const float* bout = (const float*)d_in[18];
    float* out = (float*)d_out;

    cudaFuncSetAttribute(l2_kernel, cudaFuncAttributeMaxDynamicSharedMemorySize, 2 * SHSTG * 2);
    cudaFuncSetAttribute(l3_kernel, cudaFuncAttributeMaxDynamicSharedMemorySize, 2 * UHSTG * 2);
    cudaFuncSetAttribute(o_gemm,    cudaFuncAttributeMaxDynamicSharedMemorySize, 3 * OSTG * 4);
    cudaFuncSetAttribute(ffn1_gemm, cudaFuncAttributeMaxDynamicSharedMemorySize, 2 * SHSTG * 2);
    cudaFuncSetAttribute(ffn2_gemm, cudaFuncAttributeMaxDynamicSharedMemorySize, 2 * SHSTG * 2);

    zero_kernel<<<64, 256>>>();                                        // 1
    l1_kernel<<<2048 + 176 + 1024, 256>>>(enc, Wq, bq, Wk, w1, w2);    // 2
    l2_kernel<<<2048 + NB * SKK, 256, 2 * SHSTG * 2>>>(enc);           // 3
    l3_kernel<<<1024 + NB, 256, 2 * UHSTG * 2>>>(0);                   // 4  <- ncu slot
    ctx_kernel<<<256, 256>>>(Wv, bv);                                  // 5
    dim3 go(4, 8);
    o_gemm<<<go, 256, 3 * OSTG * 4>>>(Wo, bo);                         // 6
    ln1_kernel<<<MROWS, 256>>>(g1, be1);                               // 7
    dim3 gf1(16, 8);
    ffn1_gemm<<<gf1, 256, 2 * SHSTG * 2>>>(b1);                        // 8
    dim3 gf2(4, 8, 4);
    ffn2_gemm<<<gf2, 256, 2 * SHSTG * 2>>>(0);                         // 9
    f3b_kernel<<<MROWS, 256>>>(b2, g2, be2, Wout, bout, out);          // 10
}

// round 15
// speedup vs baseline: 1.0570x; 1.0570x over previous
#include <cuda_runtime.h>
#include <cuda_fp16.h>
#include <mma.h>
#include <math.h>
#include <cstdint>

using namespace nvcuda;

#define NB   32
#define LK   4096
#define DM   512
#define NH   8
#define DH   64
#define DFF  2048
#define LQ   22
#define SKK  45
#define NTOP 20
#define ROWS 176
#define RPAD 192
#define MROWS (NB * LQ)      // 704
#define MPAD  768

// ---------------- scratch (zero-initialized device globals) ----------------
__device__ float g_qw[RPAD * DM];
__device__ __half g_qwh[256 * DM];                 // rows >=176 stay 0
__device__ __half g_ench[(size_t)NB * LK * DM];
__device__ float g_sc[NB * ROWS * 48];
__device__ unsigned char g_istop[NB * ROWS];
__device__ __half g_Sh[(size_t)NB * RPAD * LK];
__device__ float g_psum[NB * RPAD * 32];
__device__ float g_encsum[NB * DM];
__device__ __half g_uh[4 * (size_t)NB * RPAD * DM];
__device__ __half g_ctxh[MPAD * DM];               // rows >=704 stay zero
__device__ float g_ao[MROWS * DM];
__device__ float g_x[MPAD * DM];
__device__ __half g_xh[MPAD * DM];
__device__ __half g_w1h[DFF * DM];
__device__ __half g_w2h[DM * DFF];
__device__ __half g_woh[DM * DM];
__device__ __half g_ffh[(size_t)MPAD * DFF];
__device__ float g_zp[4 * (size_t)MROWS * DM];

// ---------------- async-copy helpers ----------------
__device__ __forceinline__ void cp16(void* smem, const void* gmem) {
    uint32_t s = (uint32_t)__cvta_generic_to_shared(smem);
    asm volatile("cp.async.cg.shared.global [%0], [%1], 16;" :: "r"(s), "l"(gmem));
}
__device__ __forceinline__ void cp_commit() { asm volatile("cp.async.commit_group;"); }
template<int N> __device__ __forceinline__ void cp_wait() {
    asm volatile("cp.async.wait_group %0;" :: "n"(N));
}

__device__ __forceinline__ float blockReduce(float v, float* red) {
    __syncthreads();
    #pragma unroll
    for (int o = 16; o; o >>= 1) v += __shfl_down_sync(0xffffffffu, v, o);
    int w = threadIdx.x >> 5;
    if ((threadIdx.x & 31) == 0) red[w] = v;
    __syncthreads();
    if (threadIdx.x < 32) {
        float x = (threadIdx.x < (blockDim.x >> 5)) ? red[threadIdx.x] : 0.f;
        #pragma unroll
        for (int o = 16; o; o >>= 1) x += __shfl_down_sync(0xffffffffu, x, o);
        if (threadIdx.x == 0) red[0] = x;
    }
    __syncthreads();
    return red[0];
}

// ---------------- prep: qw (0..175) | w1/w2 cvt (176..1199) | Wo cvt (1200+) -
__global__ void prep_kernel(const float* __restrict__ Wq, const float* __restrict__ bq,
                            const float* __restrict__ Wk, const float* __restrict__ Wo,
                            const float* __restrict__ w1, const float* __restrict__ w2) {
    int blk = blockIdx.x, t = threadIdx.x;
    if (blk >= 1200) {                             // Wo -> fp16
        int i = ((blk - 1200) * 256 + t) * 4;
        if (i < DM * DM) {
            float4 v = *(const float4*)(Wo + i);
            __half h4[4] = {__float2half_rn(v.x), __float2half_rn(v.y),
                            __float2half_rn(v.z), __float2half_rn(v.w)};
            *(uint2*)(g_woh + i) = *(uint2*)h4;
        }
        return;
    }
    if (blk >= 176) {                              // w1/w2 -> fp16
        int i = ((blk - 176) * 256 + t) * 4;
        if (i < DFF * DM) {
            float4 v = *(const float4*)(w1 + i);
            __half h4[4] = {__float2half_rn(v.x), __float2half_rn(v.y),
                            __float2half_rn(v.z), __float2half_rn(v.w)};
            *(uint2*)(g_w1h + i) = *(uint2*)h4;
            float4 u = *(const float4*)(w2 + i);
            __half g4[4] = {__float2half_rn(u.x), __float2half_rn(u.y),
                            __float2half_rn(u.z), __float2half_rn(u.w)};
            *(uint2*)(g_w2h + i) = *(uint2*)g4;
        }
        return;
    }
    int row = blk, h = row / LQ, q = row % LQ;
    for (int i = row * 256 + t; i < NB * DM; i += 176 * 256) g_encsum[i] = 0.f;
    __shared__ float spe[DM];
    __shared__ float sq[64];
    const float c = logf(10000.0f) / 512.0f;
    for (int j = t; j < DM; j += 256) {
        int i = j >> 1;
        float arg = (float)q * expf(-(float)(2 * i) * c);
        spe[j] = (j & 1) ? cosf(arg) : sinf(arg);
    }
    __syncthreads();
    if (t < 64) {
        float a = bq[h * 64 + t];
        for (int k = 0; k < DM; k++) a += spe[k] * Wq[k * DM + h * 64 + t];
        sq[t] = a;
    }
    __syncthreads();
    for (int c2 = t; c2 < DM; c2 += 256) {
        const float* wr = Wk + (size_t)c2 * DM + h * 64;
        float a = 0.f;
        #pragma unroll
        for (int d = 0; d < 64; d++) a += sq[d] * wr[d];
        g_qw[row * DM + c2] = a;
        g_qwh[row * DM + c2] = __float2half_rn(a);
    }
}

// ---------------- enc -> fp16 copy + column sums ----------------
__global__ void __launch_bounds__(256) enc_cvt(const float* __restrict__ enc) {
    __shared__ float ssum[DM];
    int b = blockIdx.y, l0 = blockIdx.x * 64, t = threadIdx.x;
    int c8 = (t & 63) * 8, rg = t >> 6;
    for (int i = t; i < DM; i += 256) ssum[i] = 0.f;
    __syncthreads();
    float acc[8];
    #pragma unroll
    for (int k = 0; k < 8; k++) acc[k] = 0.f;
    const float* src = enc + ((size_t)b * LK + l0) * DM + c8;
    __half* dst = g_ench + ((size_t)b * LK + l0) * DM + c8;
    #pragma unroll
    for (int i = 0; i < 16; i++) {
        int r = rg + 4 * i;
        float4 v0 = __ldg((const float4*)(src + (size_t)r * DM));
        float4 v1 = __ldg((const float4*)(src + (size_t)r * DM + 4));
        acc[0] += v0.x; acc[1] += v0.y; acc[2] += v0.z; acc[3] += v0.w;
        acc[4] += v1.x; acc[5] += v1.y; acc[6] += v1.z; acc[7] += v1.w;
        __half h8[8];
        h8[0] = __float2half_rn(v0.x); h8[1] = __float2half_rn(v0.y);
        h8[2] = __float2half_rn(v0.z); h8[3] = __float2half_rn(v0.w);
        h8[4] = __float2half_rn(v1.x); h8[5] = __float2half_rn(v1.y);
        h8[6] = __float2half_rn(v1.z); h8[7] = __float2half_rn(v1.w);
        *(uint4*)(dst + (size_t)r * DM) = *(uint4*)h8;
    }
    #pragma unroll
    for (int k = 0; k < 8; k++) atomicAdd(&ssum[c8 + k], acc[k]);
    __syncthreads();
    for (int c = t; c < DM; c += 256) atomicAdd(&g_encsum[b * DM + c], ssum[c]);
}

// ---------------- sampled scores (exact fp32) ----------------
__global__ void __launch_bounds__(256) samp_score(const float* __restrict__ enc) {
    int b = blockIdx.x / SKK, s = blockIdx.x % SKK;
    int t = threadIdx.x, warp = t >> 5, lane = t & 31;
    __shared__ float se[DM];
    int l = (s * LK) / SKK;
    for (int j = t; j < DM; j += 256) se[j] = enc[((size_t)b * LK + l) * DM + j];
    __syncthreads();
    const float4* se4 = (const float4*)se;
    for (int row = warp; row < ROWS; row += 8) {
        const float4* qw4 = (const float4*)(g_qw + row * DM);
        float a = 0.f;
        #pragma unroll
        for (int k = 0; k < 4; k++) {
            int idx = lane + k * 32;
            float4 q = qw4[idx], e = se4[idx];
            a += q.x * e.x + q.y * e.y + q.z * e.z + q.w * e.w;
        }
        #pragma unroll
        for (int o = 16; o; o >>= 1) a += __shfl_down_sync(0xffffffffu, a, o);
        if (lane == 0) g_sc[(b * ROWS + row) * 48 + s] = a;
    }
}

// ---------------- M = max-mean; stable top-20 mask ----------------
__global__ void samp_select() {
    __shared__ float sM[ROWS];
    int b = blockIdx.x, t = threadIdx.x;
    if (t < ROWS) {
        const float* sc = g_sc + (b * ROWS + t) * 48;
        float mx = -1e30f, su = 0.f;
        for (int s = 0; s < SKK; s++) { float v = sc[s]; mx = fmaxf(mx, v); su += v; }
        sM[t] = mx - su * (1.0f / SKK);
    }
    __syncthreads();
    if (t < ROWS) {
        int h = t / LQ, q = t % LQ, base = h * LQ, rank = 0;
        float mv = sM[t];
        for (int i = 0; i < LQ; i++) {
            float o = sM[base + i];
            rank += (o > mv) || (o == mv && i < q);
        }
        g_istop[b * ROWS + t] = (rank < NTOP) ? 1 : 0;
    }
}

// ---------------- S GEMM (fp16 wmma): P = exp(0.125*qW@enc^T) ----------------
#define SHSTG 16128  // halfs per stage: A 96*72 + B 128*72
__global__ void __launch_bounds__(256, 3) s_gemm(int dummy) {
    extern __shared__ __align__(16) char smraw[];
    int t = threadIdx.x, warp = t >> 5;
    int nt = blockIdx.x >> 1, mt = blockIdx.x & 1, b = blockIdx.y;
    int m0 = mt * 96, n0 = nt * 128;
    int wm = warp >> 2, wn = warp & 3;
    const __half* Ag = g_qwh + (size_t)m0 * DM;
    const __half* Bg = g_ench + ((size_t)b * LK + n0) * DM;

    auto loadStage = [&](int st, int k0) {
        __half* As = (__half*)smraw + st * SHSTG;
        __half* Bs = As + 6912;
        #pragma unroll
        for (int i4 = t; i4 < 768; i4 += 256) {
            int r = i4 >> 3, c8 = (i4 & 7) * 8;
            cp16(As + r * 72 + c8, Ag + (size_t)r * DM + k0 + c8);
        }
        #pragma unroll
        for (int i4 = t; i4 < 1024; i4 += 256) {
            int l = i4 >> 3, c8 = (i4 & 7) * 8;
            cp16(Bs + l * 72 + c8, Bg + (size_t)l * DM + k0 + c8);
        }
        cp_commit();
    };

    wmma::fragment<wmma::accumulator, 16, 16, 16, float> acc[3][2];
    #pragma unroll
    for (int i = 0; i < 3; i++)
        #pragma unroll
        for (int j = 0; j < 2; j++) wmma::fill_fragment(acc[i][j], 0.0f);

    loadStage(0, 0);
    for (int ks = 0; ks < 8; ks++) {
        cp_wait<0>();
        __syncthreads();
        if (ks + 1 < 8) loadStage((ks + 1) & 1, (ks + 1) * 64);
        __half* As = (__half*)smraw + (ks & 1) * SHSTG;
        __half* Bs = As + 6912;
        #pragma unroll
        for (int kk = 0; kk < 4; kk++) {
            wmma::fragment<wmma::matrix_a, 16, 16, 16, __half, wmma::row_major> af[3];
            wmma::fragment<wmma::matrix_b, 16, 16, 16, __half, wmma::col_major> bf[2];
            #pragma unroll
            for (int i = 0; i < 3; i++)
                wmma::load_matrix_sync(af[i], As + (wm * 48 + i * 16) * 72 + kk * 16, 72);
            #pragma unroll
            for (int j = 0; j < 2; j++)
                wmma::load_matrix_sync(bf[j], Bs + (wn * 32 + j * 16) * 72 + kk * 16, 72);
            #pragma unroll
            for (int i = 0; i < 3; i++)
                #pragma unroll
                for (int j = 0; j < 2; j++) wmma::mma_sync(acc[i][j], af[i], bf[j], acc[i][j]);
        }
    }
    __syncthreads();
    float* Ss = (float*)smraw;  // [96][132]
    #pragma unroll
    for (int i = 0; i < 3; i++)
        #pragma unroll
        for (int j = 0; j < 2; j++)
            wmma::store_matrix_sync(Ss + (wm * 48 + i * 16) * 132 + wn * 32 + j * 16,
                                    acc[i][j], 132, wmma::mem_row_major);
    __syncthreads();
    size_t base = ((size_t)b * RPAD + m0) * LK + n0;
    __shared__ float srow[96];
    if (t < 96) srow[t] = 0.f;
    __syncthreads();
    int lane = t & 31;
    for (int i4 = t; i4 < 3072; i4 += 256) {
        int r = i4 >> 5, c4 = (i4 & 31) * 4;
        float4 v = *(float4*)(Ss + r * 132 + c4);
        float e0 = __expf(v.x * 0.125f), e1 = __expf(v.y * 0.125f);
        float e2 = __expf(v.z * 0.125f), e3 = __expf(v.w * 0.125f);
        __half h4[4];
        h4[0] = __float2half_rn(e0); h4[1] = __float2half_rn(e1);
        h4[2] = __float2half_rn(e2); h4[3] = __float2half_rn(e3);
        *(uint2*)(g_Sh + base + (size_t)r * LK + c4) = *(uint2*)h4;
        float s4 = e0 + e1 + e2 + e3;
        #pragma unroll
        for (int o = 16; o; o >>= 1) s4 += __shfl_down_sync(0xffffffffu, s4, o);
        if (lane == 0) srow[r] = s4;
    }
    __syncthreads();
    if (t < 96) g_psum[((size_t)b * RPAD + m0 + t) * 32 + nt] = srow[t];
}

// ---------------- u GEMM (fp16 wmma): u = P @ enc, kc=4, k-chunk 64, 2-stage -
#define UHSTG 15616  // halfs per stage: A 96*72 + B 64*136
__global__ void __launch_bounds__(256, 3) u_gemm(int dummy) {
    extern __shared__ __align__(16) char smraw[];
    int t = threadIdx.x, warp = t >> 5;
    int gx = blockIdx.x, b = blockIdx.y;
    int nt = gx & 3, mt = (gx >> 2) & 1, kc = gx >> 3;
    int m0 = mt * 96, n0 = nt * 128;
    int wm = warp >> 2, wn = warp & 3;
    const __half* Ag = g_Sh + ((size_t)b * RPAD + m0) * LK + kc * 1024;
    const __half* Bg = g_ench + ((size_t)b * LK + kc * 1024) * DM + n0;

    auto loadStage = [&](int st, int k0) {
        __half* As = (__half*)smraw + st * UHSTG;
        __half* Bs = As + 6912;
        #pragma unroll
        for (int i4 = t; i4 < 768; i4 += 256) {
            int r = i4 >> 3, c8 = (i4 & 7) * 8;
            cp16(As + r * 72 + c8, Ag + (size_t)r * LK + k0 + c8);
        }
        #pragma unroll
        for (int i4 = t; i4 < 1024; i4 += 256) {
            int l = i4 >> 4, c8 = (i4 & 15) * 8;
            cp16(Bs + l * 136 + c8, Bg + (size_t)(k0 + l) * DM + c8);
        }
        cp_commit();
    };

    wmma::fragment<wmma::accumulator, 16, 16, 16, float> acc[3][2];
    #pragma unroll
    for (int i = 0; i < 3; i++)
        #pragma unroll
        for (int j = 0; j < 2; j++) wmma::fill_fragment(acc[i][j], 0.0f);

    loadStage(0, 0);
    for (int ks = 0; ks < 16; ks++) {
        cp_wait<0>();
        __syncthreads();
        if (ks + 1 < 16) loadStage((ks + 1) & 1, (ks + 1) * 64);
        __half* As = (__half*)smraw + (ks & 1) * UHSTG;
        __half* Bs = As + 6912;
        #pragma unroll
        for (int kk = 0; kk < 4; kk++) {
            wmma::fragment<wmma::matrix_a, 16, 16, 16, __half, wmma::row_major> af[3];
            wmma::fragment<wmma::matrix_b, 16, 16, 16, __half, wmma::row_major> bf[2];
            #pragma unroll
            for (int i = 0; i < 3; i++)
                wmma::load_matrix_sync(af[i], As + (wm * 48 + i * 16) * 72 + kk * 16, 72);
            #pragma unroll
            for (int j = 0; j < 2; j++)
                wmma::load_matrix_sync(bf[j], Bs + (kk * 16) * 136 + wn * 32 + j * 16, 136);
            #pragma unroll
            for (int i = 0; i < 3; i++)
                #pragma unroll
                for (int j = 0; j < 2; j++) wmma::mma_sync(acc[i][j], af[i], bf[j], acc[i][j]);
        }
    }
    __syncthreads();
    float* Ss = (float*)smraw;  // [96][132]
    #pragma unroll
    for (int i = 0; i < 3; i++)
        #pragma unroll
        for (int j = 0; j < 2; j++)
            wmma::store_matrix_sync(Ss + (wm * 48 + i * 16) * 132 + wn * 32 + j * 16,
                                    acc[i][j], 132, wmma::mem_row_major);
    __syncthreads();
    __half* up = g_uh + (size_t)kc * NB * RPAD * DM + ((size_t)(b * RPAD + m0)) * DM + n0;
    for (int i4 = t; i4 < 3072; i4 += 256) {
        int r = i4 >> 5, c4 = (i4 & 31) * 4;
        float4 v = *(float4*)(Ss + r * 132 + c4);
        __half h4[4];
        h4[0] = __float2half_rn(v.x); h4[1] = __float2half_rn(v.y);
        h4[2] = __float2half_rn(v.z); h4[3] = __float2half_rn(v.w);
        *(uint2*)(up + (size_t)r * DM + c4) = *(uint2*)h4;
    }
}

// ---------------- ctx: rinv inline; outputs fp16 g_ctxh ----------------
__global__ void ctx_kernel(const float* __restrict__ Wv, const float* __restrict__ bv) {
    __shared__ float su[LQ * DM];
    __shared__ float svm[64];
    __shared__ float srinv[LQ];
    int bh = blockIdx.x, b = bh >> 3, h = bh & 7, t = threadIdx.x;
    const size_t ub = ((size_t)b * RPAD + h * LQ) * DM;
    const size_t part = (size_t)NB * RPAD * DM;
    if (t < LQ) {
        const float* ps = g_psum + ((size_t)b * RPAD + h * LQ + t) * 32;
        float s = 0.f;
        #pragma unroll
        for (int i = 0; i < 32; i++) s += ps[i];
        srinv[t] = 1.0f / s;
    }
    __syncthreads();
    for (int i = t; i < LQ * DM; i += 256) {
        int q = i >> 9;
        float s = __half2float(g_uh[ub + i]) + __half2float(g_uh[part + ub + i])
                + __half2float(g_uh[2 * part + ub + i]) + __half2float(g_uh[3 * part + ub + i]);
        su[i] = s * srinv[q];
    }
    if (t < 64) {
        float a = bv[h * 64 + t];
        const float inv = 1.0f / 4096.f;
        for (int c = 0; c < DM; c++) a += g_encsum[b * DM + c] * inv * Wv[c * DM + h * 64 + t];
        svm[t] = a;
    }
    __syncthreads();
    for (int i = t; i < LQ * 64; i += 256) {
        int q = i >> 6, d = i & 63;
        float v;
        if (g_istop[b * ROWS + h * LQ + q]) {
            float a = bv[h * 64 + d];
            for (int c = 0; c < DM; c++) a += su[q * DM + c] * Wv[c * DM + h * 64 + d];
            v = a;
        } else v = svm[d];
        g_ctxh[((size_t)b * LQ + q) * DM + h * 64 + d] = __float2half_rn(v);
    }
}

// ---------------- o GEMM (fp16): g_ao = 2*(ctx @ Wo + bo), 2-stage -----------
__global__ void __launch_bounds__(256, 3) o_gemm(const float* __restrict__ bo) {
    extern __shared__ __align__(16) char smraw[];
    int t = threadIdx.x, warp = t >> 5;
    int m0 = blockIdx.y * 96, n0 = blockIdx.x * 128;
    int wm = warp >> 2, wn = warp & 3;
    const __half* Ag = g_ctxh + (size_t)m0 * DM;
    const __half* Bg = g_woh + n0;

    auto loadStage = [&](int st, int k0) {
        __half* As = (__half*)smraw + st * UHSTG;
        __half* Bs = As + 6912;
        #pragma unroll
        for (int i4 = t; i4 < 768; i4 += 256) {
            int r = i4 >> 3, c8 = (i4 & 7) * 8;
            cp16(As + r * 72 + c8, Ag + (size_t)r * DM + k0 + c8);
        }
        #pragma unroll
        for (int i4 = t; i4 < 1024; i4 += 256) {
            int l = i4 >> 4, c8 = (i4 & 15) * 8;
            cp16(Bs + l * 136 + c8, Bg + (size_t)(k0 + l) * DM + c8);
        }
        cp_commit();
    };

    wmma::fragment<wmma::accumulator, 16, 16, 16, float> acc[3][2];
    #pragma unroll
    for (int i = 0; i < 3; i++)
        #pragma unroll
        for (int j = 0; j < 2; j++) wmma::fill_fragment(acc[i][j], 0.0f);

    loadStage(0, 0);
    for (int ks = 0; ks < 8; ks++) {
        cp_wait<0>();
        __syncthreads();
        if (ks + 1 < 8) loadStage((ks + 1) & 1, (ks + 1) * 64);
        __half* As = (__half*)smraw + (ks & 1) * UHSTG;
        __half* Bs = As + 6912;
        #pragma unroll
        for (int kk = 0; kk < 4; kk++) {
            wmma::fragment<wmma::matrix_a, 16, 16, 16, __half, wmma::row_major> af[3];
            wmma::fragment<wmma::matrix_b, 16, 16, 16, __half, wmma::row_major> bf[2];
            #pragma unroll
            for (int i = 0; i < 3; i++)
                wmma::load_matrix_sync(af[i], As + (wm * 48 + i * 16) * 72 + kk * 16, 72);
            #pragma unroll
            for (int j = 0; j < 2; j++)
                wmma::load_matrix_sync(bf[j], Bs + (kk * 16) * 136 + wn * 32 + j * 16, 136);
            #pragma unroll
            for (int i = 0; i < 3; i++)
                #pragma unroll
                for (int j = 0; j < 2; j++) wmma::mma_sync(acc[i][j], af[i], bf[j], acc[i][j]);
        }
    }
    __syncthreads();
    float* Ss = (float*)smraw;
    #pragma unroll
    for (int i = 0; i < 3; i++)
        #pragma unroll
        for (int j = 0; j < 2; j++)
            wmma::store_matrix_sync(Ss + (wm * 48 + i * 16) * 132 + wn * 32 + j * 16,
                                    acc[i][j], 132, wmma::mem_row_major);
    __syncthreads();
    for (int i4 = t; i4 < 3072; i4 += 256) {
        int r = i4 >> 5, c4 = (i4 & 31) * 4;
        int row = m0 + r, n = n0 + c4;
        if (row >= MROWS) continue;
        float4 v = *(float4*)(Ss + r * 132 + c4);
        v.x = 2.0f * (v.x + bo[n + 0]); v.y = 2.0f * (v.y + bo[n + 1]);
        v.z = 2.0f * (v.z + bo[n + 2]); v.w = 2.0f * (v.w + bo[n + 3]);
        *(float4*)(g_ao + (size_t)row * DM + n) = v;
    }
}

// ---------------- ln1: x = LN(g_ao) (fp32 + fp16) ----------------
__global__ void ln1_kernel(const float* __restrict__ g1, const float* __restrict__ be1) {
    int r = blockIdx.x, t = threadIdx.x;
    __shared__ float red[32];
    float z0 = g_ao[(size_t)r * DM + t];
    float z1 = g_ao[(size_t)r * DM + t + 256];
    float s1 = blockReduce(z0 + z1, red);
    float s2 = blockReduce(z0 * z0 + z1 * z1, red);
    float mu = s1 * (1.0f / 512.f);
    float va = fmaxf(s2 * (1.0f / 512.f) - mu * mu, 0.f);
    float rs = rsqrtf(va + 1e-5f);
    float x0 = (z0 - mu) * rs * g1[t] + be1[t];
    float x1 = (z1 - mu) * rs * g1[t + 256] + be1[t + 256];
    g_x[(size_t)r * DM + t] = x0;
    g_x[(size_t)r * DM + t + 256] = x1;
    g_xh[(size_t)r * DM + t] = __float2half_rn(x0);
    g_xh[(size_t)r * DM + t + 256] = __float2half_rn(x1);
}

// ---------------- ffn1 (fp16 wmma): g_ffh = relu(x @ w1^T + b1), 2-stage -----
__global__ void __launch_bounds__(256, 3) ffn1_gemm(const float* __restrict__ b1) {
    extern __shared__ __align__(16) char smraw[];
    int t = threadIdx.x, warp = t >> 5;
    int m0 = blockIdx.y * 96, n0 = blockIdx.x * 128;
    int wm = warp >> 2, wn = warp & 3;
    const __half* Ag = g_xh + (size_t)m0 * DM;
    const __half* Bg = g_w1h + (size_t)n0 * DM;

    auto loadStage = [&](int st, int k0) {
        __half* As = (__half*)smraw + st * SHSTG;
        __half* Bs = As + 6912;
        #pragma unroll
        for (int i4 = t; i4 < 768; i4 += 256) {
            int r = i4 >> 3, c8 = (i4 & 7) * 8;
            cp16(As + r * 72 + c8, Ag + (size_t)r * DM + k0 + c8);
        }
        #pragma unroll
        for (int i4 = t; i4 < 1024; i4 += 256) {
            int n = i4 >> 3, c8 = (i4 & 7) * 8;
            cp16(Bs + n * 72 + c8, Bg + (size_t)n * DM + k0 + c8);
        }
        cp_commit();
    };

    wmma::fragment<wmma::accumulator, 16, 16, 16, float> acc[3][2];
    #pragma unroll
    for (int i = 0; i < 3; i++)
        #pragma unroll
        for (int j = 0; j < 2; j++) wmma::fill_fragment(acc[i][j], 0.0f);

    loadStage(0, 0);
    for (int ks = 0; ks < 8; ks++) {
        cp_wait<0>();
        __syncthreads();
        if (ks + 1 < 8) loadStage((ks + 1) & 1, (ks + 1) * 64);
        __half* As = (__half*)smraw + (ks & 1) * SHSTG;
        __half* Bs = As + 6912;
        #pragma unroll
        for (int kk = 0; kk < 4; kk++) {
            wmma::fragment<wmma::matrix_a, 16, 16, 16, __half, wmma::row_major> af[3];
            wmma::fragment<wmma::matrix_b, 16, 16, 16, __half, wmma::col_major> bf[2];
            #pragma unroll
            for (int i = 0; i < 3; i++)
                wmma::load_matrix_sync(af[i], As + (wm * 48 + i * 16) * 72 + kk * 16, 72);
            #pragma unroll
            for (int j = 0; j < 2; j++)
                wmma::load_matrix_sync(bf[j], Bs + (wn * 32 + j * 16) * 72 + kk * 16, 72);
            #pragma unroll
            for (int i = 0; i < 3; i++)
                #pragma unroll
                for (int j = 0; j < 2; j++) wmma::mma_sync(acc[i][j], af[i], bf[j], acc[i][j]);
        }
    }
    __syncthreads();
    float* Ss = (float*)smraw;
    #pragma unroll
    for (int i = 0; i < 3; i++)
        #pragma unroll
        for (int j = 0; j < 2; j++)
            wmma::store_matrix_sync(Ss + (wm * 48 + i * 16) * 132 + wn * 32 + j * 16,
                                    acc[i][j], 132, wmma::mem_row_major);
    __syncthreads();
    for (int i4 = t; i4 < 3072; i4 += 256) {
        int r = i4 >> 5, c4 = (i4 & 31) * 4;
        int row = m0 + r, n = n0 + c4;
        if (row >= MROWS) continue;
        float4 v = *(float4*)(Ss + r * 132 + c4);
        __half h4[4];
        h4[0] = __float2half_rn(fmaxf(v.x + b1[n + 0], 0.f));
        h4[1] = __float2half_rn(fmaxf(v.y + b1[n + 1], 0.f));
        h4[2] = __float2half_rn(fmaxf(v.z + b1[n + 2], 0.f));
        h4[3] = __float2half_rn(fmaxf(v.w + b1[n + 3], 0.f));
        *(uint2*)(g_ffh + (size_t)row * DFF + n) = *(uint2*)h4;
    }
}

// ---------------- ffn2 (fp16 wmma): g_zp[kc] = ff[:,kc]@w2[:,kc]^T, 2-stage --
__global__ void __launch_bounds__(256, 3) ffn2_gemm(int dummy) {
    extern __shared__ __align__(16) char smraw[];
    int t = threadIdx.x, warp = t >> 5;
    int m0 = blockIdx.y * 96, n0 = blockIdx.x * 128, kc = blockIdx.z;
    int wm = warp >> 2, wn = warp & 3;
    const __half* Ag = g_ffh + (size_t)m0 * DFF + kc * 512;
    const __half* Bg = g_w2h + (size_t)n0 * DFF + kc * 512;

    auto loadStage = [&](int st, int k0) {
        __half* As = (__half*)smraw + st * SHSTG;
        __half* Bs = As + 6912;
        #pragma unroll
        for (int i4 = t; i4 < 768; i4 += 256) {
            int r = i4 >> 3, c8 = (i4 & 7) * 8;
            cp16(As + r * 72 + c8, Ag + (size_t)r * DFF + k0 + c8);
        }
        #pragma unroll
        for (int i4 = t; i4 < 1024; i4 += 256) {
            int n = i4 >> 3, c8 = (i4 & 7) * 8;
            cp16(Bs + n * 72 + c8, Bg + (size_t)n * DFF + k0 + c8);
        }
        cp_commit();
    };

    wmma::fragment<wmma::accumulator, 16, 16, 16, float> acc[3][2];
    #pragma unroll
    for (int i = 0; i < 3; i++)
        #pragma unroll
        for (int j = 0; j < 2; j++) wmma::fill_fragment(acc[i][j], 0.0f);

    loadStage(0, 0);
    for (int ks = 0; ks < 8; ks++) {
        cp_wait<0>();
        __syncthreads();
        if (ks + 1 < 8) loadStage((ks + 1) & 1, (ks + 1) * 64);
        __half* As = (__half*)smraw + (ks & 1) * SHSTG;
        __half* Bs = As + 6912;
        #pragma unroll
        for (int kk = 0; kk < 4; kk++) {
            wmma::fragment<wmma::matrix_a, 16, 16, 16, __half, wmma::row_major> af[3];
            wmma::fragment<wmma::matrix_b, 16, 16, 16, __half, wmma::col_major> bf[2];
            #pragma unroll
            for (int i = 0; i < 3; i++)
                wmma::load_matrix_sync(af[i], As + (wm * 48 + i * 16) * 72 + kk * 16, 72);
            #pragma unroll
            for (int j = 0; j < 2; j++)
                wmma::load_matrix_sync(bf[j], Bs + (wn * 32 + j * 16) * 72 + kk * 16, 72);
            #pragma unroll
            for (int i = 0; i < 3; i++)
                #pragma unroll
                for (int j = 0; j < 2; j++) wmma::mma_sync(acc[i][j], af[i], bf[j], acc[i][j]);
        }
    }
    __syncthreads();
    float* Ss = (float*)smraw;
    #pragma unroll
    for (int i = 0; i < 3; i++)
        #pragma unroll
        for (int j = 0; j < 2; j++)
            wmma::store_matrix_sync(Ss + (wm * 48 + i * 16) * 132 + wn * 32 + j * 16,
                                    acc[i][j], 132, wmma::mem_row_major);
    __syncthreads();
    float* Cp = g_zp + (size_t)kc * MROWS * DM;
    for (int i4 = t; i4 < 3072; i4 += 256) {
        int r = i4 >> 5, c4 = (i4 & 31) * 4;
        int row = m0 + r, n = n0 + c4;
        if (row >= MROWS) continue;
        *(float4*)(Cp + (size_t)row * DM + n) = *(float4*)(Ss + r * 132 + c4);
    }
}

// ---------------- f3b: z = x + b2 + sum partials; y = LN(z); forecast --------
__global__ void f3b_kernel(const float* __restrict__ b2,
                           const float* __restrict__ g2, const float* __restrict__ be2,
                           const float* __restrict__ Wout, const float* __restrict__ bout,
                           float* __restrict__ out) {
    int r = blockIdx.x, t = threadIdx.x;
    __shared__ float red[32];
    const size_t part = (size_t)MROWS * DM;
    size_t o0 = (size_t)r * DM + t, o1 = o0 + 256;
    float z0 = g_x[o0] + b2[t] + g_zp[o0] + g_zp[part + o0] + g_zp[2 * part + o0] + g_zp[3 * part + o0];
    float z1 = g_x[o1] + b2[t + 256] + g_zp[o1] + g_zp[part + o1] + g_zp[2 * part + o1] + g_zp[3 * part + o1];
    float s1 = blockReduce(z0 + z1, red);
    float s2 = blockReduce(z0 * z0 + z1 * z1, red);
    float mu = s1 * (1.0f / 512.f);
    float va = fmaxf(s2 * (1.0f / 512.f) - mu * mu, 0.f);
    float rs = rsqrtf(va + 1e-5f);
    float y0 = (z0 - mu) * rs * g2[t] + be2[t];
    float y1 = (z1 - mu) * rs * g2[t + 256] + be2[t + 256];
    out[NB * LQ + (size_t)r * DM + t] = y0;
    out[NB * LQ + (size_t)r * DM + t + 256] = y1;
    float f = blockReduce(y0 * Wout[t] + y1 * Wout[t + 256], red);
    if (t == 0) out[r] = f + bout[0];
}

// ---------------- launch ----------------
extern "C" void kernel_launch(void* const* d_in, const int* in_sizes, int n_in,
                              void* d_out, int out_size) {
    const float* enc  = (const float*)d_in[0];
    const float* Wq   = (const float*)d_in[1];
    const float* bq   = (const float*)d_in[2];
    const float* Wk   = (const float*)d_in[3];
    const float* Wv   = (const float*)d_in[5];
    const float* bv   = (const float*)d_in[6];
    const float* Wo   = (const float*)d_in[7];
    const float* bo   = (const float*)d_in[8];
    const float* w1   = (const float*)d_in[9];
    const float* b1   = (const float*)d_in[10];
    const float* w2   = (const float*)d_in[11];
    const float* b2   = (const float*)d_in[12];
    const float* g1   = (const float*)d_in[13];
    const float* be1  = (const float*)d_in[14];
    const float* g2   = (const float*)d_in[15];
    const float* be2  = (const float*)d_in[16];
    const float* Wout = (const float*)d_in[17];
    const float* bout = (const float*)d_in[18];
    float* out = (float*)d_out;

    cudaFuncSetAttribute(s_gemm,    cudaFuncAttributeMaxDynamicSharedMemorySize, 2 * SHSTG * 2);
    cudaFuncSetAttribute(u_gemm,    cudaFuncAttributeMaxDynamicSharedMemorySize, 2 * UHSTG * 2);
    cudaFuncSetAttribute(o_gemm,    cudaFuncAttributeMaxDynamicSharedMemorySize, 2 * UHSTG * 2);
    cudaFuncSetAttribute(ffn1_gemm, cudaFuncAttributeMaxDynamicSharedMemorySize, 2 * SHSTG * 2);
    cudaFuncSetAttribute(ffn2_gemm, cudaFuncAttributeMaxDynamicSharedMemorySize, 2 * SHSTG * 2);

    prep_kernel<<<1200 + 256, 256>>>(Wq, bq, Wk, Wo, w1, w2);     // 1 (+zero encsum)
    dim3 gcv(LK / 64, NB);
    enc_cvt<<<gcv, 256>>>(enc);                                   // 2
    samp_score<<<NB * SKK, 256>>>(enc);                           // 3
    dim3 gc(64, NB);
    s_gemm<<<gc, 256, 2 * SHSTG * 2>>>(0);                        // 4  <- ncu slot
    samp_select<<<NB, 256>>>();                                   // 5
    dim3 ge(32, NB);
    u_gemm<<<ge, 256, 2 * UHSTG * 2>>>(0);                        // 6
    ctx_kernel<<<256, 256>>>(Wv, bv);                             // 7
    dim3 go(4, 8);
    o_gemm<<<go, 256, 2 * UHSTG * 2>>>(bo);                       // 8
    ln1_kernel<<<MROWS, 256>>>(g1, be1);                          // 9
    dim3 gf1(16, 8);
    ffn1_gemm<<<gf1, 256, 2 * SHSTG * 2>>>(b1);                   // 10
    dim3 gf2(4, 8, 4);
    ffn2_gemm<<<gf2, 256, 2 * SHSTG * 2>>>(0);                    // 11
    f3b_kernel<<<MROWS, 256>>>(b2, g2, be2, Wout, bout, out);     // 12
}